// round 1
// baseline (speedup 1.0000x reference)
#include <cuda_runtime.h>
#include <math.h>

#define NB      4
#define TSEQ    2048
#define NHEAD   16
#define HD      64
#define DMODEL  1024
#define ROWS    (NB * TSEQ)          // 8192
#define QKVCOLS (3 * DMODEL)         // 3072
#define WIN     128

// Scratch (static device globals: allocation-free rule)
__device__ float g_qkv[ROWS * QKVCOLS];     // [b,t, 3, h, d]
__device__ float g_attn[ROWS * DMODEL];     // [b,t, h, d]

// ---------------------------------------------------------------------------
// SGEMM: C[M,N] = A[M,K] * B[K,N] (+ bias[N]). M%128==0, N%128==0, K%16==0.
// 128x128 block tile, 8x8 per thread, 256 threads.
// ---------------------------------------------------------------------------
template <int BM, int BN, int BK, int TM, int TN>
__global__ __launch_bounds__(256, 2)
void sgemm_kernel(const float* __restrict__ A, const float* __restrict__ B,
                  float* __restrict__ C, int M, int N, int K,
                  const float* __restrict__ bias)
{
    __shared__ __align__(16) float As[BK][BM];
    __shared__ __align__(16) float Bs[BK][BN];

    const int tid = threadIdx.x;
    const int block_row = blockIdx.y * BM;
    const int block_col = blockIdx.x * BN;

    // A tile loads: BM x BK, transposed into As[k][m]
    const int a_row = tid / (BK / 4);            // 0..63
    const int a_col = (tid % (BK / 4)) * 4;      // 0,4,8,12
    // B tile loads: BK x BN
    const int b_row = tid / (BN / 4);            // 0..7
    const int b_col = (tid % (BN / 4)) * 4;

    const int trow = (tid / (BN / TN)) * TM;
    const int tcol = (tid % (BN / TN)) * TN;

    float acc[TM][TN];
#pragma unroll
    for (int i = 0; i < TM; i++)
#pragma unroll
        for (int j = 0; j < TN; j++) acc[i][j] = 0.0f;

    const float* Aptr = A + (size_t)block_row * K;
    const float* Bptr = B + block_col;

    for (int k0 = 0; k0 < K; k0 += BK) {
#pragma unroll
        for (int r = a_row; r < BM; r += 64) {
            float4 v = *(const float4*)(Aptr + (size_t)r * K + k0 + a_col);
            As[a_col + 0][r] = v.x;
            As[a_col + 1][r] = v.y;
            As[a_col + 2][r] = v.z;
            As[a_col + 3][r] = v.w;
        }
#pragma unroll
        for (int r = b_row; r < BK; r += 8) {
            *(float4*)(&Bs[r][b_col]) =
                *(const float4*)(Bptr + (size_t)(k0 + r) * N + b_col);
        }
        __syncthreads();

#pragma unroll
        for (int k = 0; k < BK; k++) {
            float4 m0 = *(const float4*)(&As[k][trow]);
            float4 m1 = *(const float4*)(&As[k][trow + 4]);
            float4 n0 = *(const float4*)(&Bs[k][tcol]);
            float4 n1 = *(const float4*)(&Bs[k][tcol + 4]);
            float regM[TM] = {m0.x, m0.y, m0.z, m0.w, m1.x, m1.y, m1.z, m1.w};
            float regN[TN] = {n0.x, n0.y, n0.z, n0.w, n1.x, n1.y, n1.z, n1.w};
#pragma unroll
            for (int i = 0; i < TM; i++)
#pragma unroll
                for (int j = 0; j < TN; j++)
                    acc[i][j] = fmaf(regM[i], regN[j], acc[i][j]);
        }
        __syncthreads();
    }

#pragma unroll
    for (int i = 0; i < TM; i++) {
        float* crow = C + (size_t)(block_row + trow + i) * N + block_col + tcol;
#pragma unroll
        for (int j = 0; j < TN; j += 4) {
            float4 v;
            v.x = acc[i][j + 0];
            v.y = acc[i][j + 1];
            v.z = acc[i][j + 2];
            v.w = acc[i][j + 3];
            if (bias) {
                const float* bp = bias + block_col + tcol + j;
                v.x += bp[0]; v.y += bp[1]; v.z += bp[2]; v.w += bp[3];
            }
            *(float4*)(crow + j) = v;
        }
    }
}

// ---------------------------------------------------------------------------
// RoPE applied in-place to Q and K inside g_qkv.
// ROTARY_DIM == HEAD_DIM == 64 -> every element is rotated.
// thread handles one (row, comp in {q,k}, head, pair-index i in [0,32))
// ---------------------------------------------------------------------------
__global__ void rope_kernel()
{
    int idx = blockIdx.x * blockDim.x + threadIdx.x;
    const int total = ROWS * 2 * NHEAD * 32;
    if (idx >= total) return;

    int i = idx & 31;            // freq index
    int tmp = idx >> 5;
    int h = tmp & (NHEAD - 1);
    tmp >>= 4;
    int comp = tmp & 1;          // 0 = q, 1 = k
    int row = tmp >> 1;          // b*T + t
    int t = row & (TSEQ - 1);

    // inv_freq = 10000^(-(2i)/64); log2(10000) = 13.287712379549449
    float e = (float)(2 * i) * (1.0f / 64.0f);
    float inv_freq = exp2f(-e * 13.2877123795494493f);
    float ang = (float)t * inv_freq;
    float c, s;
    sincosf(ang, &s, &c);  // note: sincosf(x, &sin, &cos)

    float* base = g_qkv + (size_t)row * QKVCOLS + comp * DMODEL + h * HD;
    float x1 = base[i];
    float x2 = base[i + 32];
    base[i]      = x1 * c - x2 * s;
    base[i + 32] = x1 * s + x2 * c;
}

// ---------------------------------------------------------------------------
// Sliding-window attention. One warp per (b, h, t) query.
// lane owns dims {2*lane, 2*lane+1}. Online softmax, warp-uniform max branch.
// ---------------------------------------------------------------------------
__global__ __launch_bounds__(256)
void attn_kernel()
{
    int w = (blockIdx.x * blockDim.x + threadIdx.x) >> 5;
    int lane = threadIdx.x & 31;
    // w -> (b, h, t), t fastest so adjacent warps share key windows
    int t = w & (TSEQ - 1);
    int tmp = w >> 11;
    int h = tmp & (NHEAD - 1);
    int b = tmp >> 4;

    const float* qp = g_qkv + (size_t)(b * TSEQ + t) * QKVCOLS + h * HD + 2 * lane;
    float2 q = *(const float2*)qp;
    q.x *= 0.125f;  // fold 1/sqrt(64) into q
    q.y *= 0.125f;

    int j0 = t - WIN; if (j0 < 0) j0 = 0;
    int j1 = t + WIN; if (j1 > TSEQ - 1) j1 = TSEQ - 1;

    const float* kbase = g_qkv + (size_t)b * TSEQ * QKVCOLS + DMODEL + h * HD + 2 * lane;

    float m = -INFINITY;
    float l = 0.0f;
    float2 acc = {0.0f, 0.0f};

    for (int j = j0; j <= j1; j++) {
        const float* kp = kbase + (size_t)j * QKVCOLS;
        float2 kv = *(const float2*)kp;
        float s = q.x * kv.x + q.y * kv.y;
#pragma unroll
        for (int off = 16; off; off >>= 1)
            s += __shfl_xor_sync(0xffffffffu, s, off);
        float2 vv = *(const float2*)(kp + DMODEL);  // V is +1024 past K
        if (s > m) {  // warp-uniform after reduce: non-divergent
            float corr = __expf(m - s);
            l *= corr;
            acc.x *= corr;
            acc.y *= corr;
            m = s;
        }
        float p = __expf(s - m);
        l += p;
        acc.x = fmaf(p, vv.x, acc.x);
        acc.y = fmaf(p, vv.y, acc.y);
    }

    float inv = 1.0f / l;
    float2 o = {acc.x * inv, acc.y * inv};
    *(float2*)(g_attn + (size_t)(b * TSEQ + t) * DMODEL + h * HD + 2 * lane) = o;
}

// ---------------------------------------------------------------------------
extern "C" void kernel_launch(void* const* d_in, const int* in_sizes, int n_in,
                              void* d_out, int out_size)
{
    const float* x    = (const float*)d_in[0];   // [4,2048,1024]
    const float* Wqkv = (const float*)d_in[1];   // [1024,3072]
    const float* Wout = (const float*)d_in[2];   // [1024,1024]
    const float* bout = (const float*)d_in[3];   // [1024]
    float* out = (float*)d_out;                  // [4,2048,1024]

    float* qkv;
    float* attn;
    cudaGetSymbolAddress((void**)&qkv,  g_qkv);
    cudaGetSymbolAddress((void**)&attn, g_attn);

    // 1) QKV projection
    {
        dim3 grid(QKVCOLS / 128, ROWS / 128);
        sgemm_kernel<128, 128, 16, 8, 8><<<grid, 256>>>(
            x, Wqkv, qkv, ROWS, QKVCOLS, DMODEL, nullptr);
    }
    // 2) RoPE on Q and K in-place
    {
        int total = ROWS * 2 * NHEAD * 32;
        rope_kernel<<<(total + 255) / 256, 256>>>();
    }
    // 3) Sliding-window attention
    {
        int warps = NB * NHEAD * TSEQ;             // 131072
        attn_kernel<<<warps / 8, 256>>>();
    }
    // 4) Output projection + bias
    {
        dim3 grid(DMODEL / 128, ROWS / 128);
        sgemm_kernel<128, 128, 16, 8, 8><<<grid, 256>>>(
            attn, Wout, out, ROWS, DMODEL, DMODEL, bout);
    }
}

// round 3
// speedup vs baseline: 1.7561x; 1.7561x over previous
#include <cuda_runtime.h>
#include <cuda_bf16.h>
#include <math.h>
#include <stdint.h>

#define NB      4
#define TSEQ    2048
#define NHEAD   16
#define HD      64
#define DMODEL  1024
#define ROWS    (NB * TSEQ)          // 8192
#define QKVCOLS (3 * DMODEL)         // 3072
#define WIN     128

// ---------------- scratch (allocation-free rule: device globals) ----------
__device__ float g_qkv [ROWS * QKVCOLS];                 // [b,t, 3,h,d]
__device__ float g_attn[ROWS * DMODEL];                  // [b,t, h,d]
__device__ __align__(16) __nv_bfloat16 g_Ah[ROWS   * DMODEL];
__device__ __align__(16) __nv_bfloat16 g_Al[ROWS   * DMODEL];
__device__ __align__(16) __nv_bfloat16 g_Bh[QKVCOLS * DMODEL];  // [N][K] transposed
__device__ __align__(16) __nv_bfloat16 g_Bl[QKVCOLS * DMODEL];

// ---------------- PTX helpers ---------------------------------------------
__device__ __forceinline__ uint32_t smem_u32(const void* p) {
    uint32_t a;
    asm("{ .reg .u64 t; cvta.to.shared.u64 t, %1; cvt.u32.u64 %0, t; }" : "=r"(a) : "l"(p));
    return a;
}
__device__ __forceinline__ void cp16(uint32_t dst, const void* src) {
    asm volatile("cp.async.cg.shared.global [%0], [%1], 16;" :: "r"(dst), "l"(src));
}
#define CP_COMMIT() asm volatile("cp.async.commit_group;" ::: "memory")
#define CP_WAIT(n)  asm volatile("cp.async.wait_group %0;" :: "n"(n) : "memory")

#define LDSM_X4(r, addr) \
    asm volatile("ldmatrix.sync.aligned.m8n8.x4.shared.b16 {%0,%1,%2,%3}, [%4];" \
        : "=r"((r)[0]), "=r"((r)[1]), "=r"((r)[2]), "=r"((r)[3]) : "r"(addr))

#define MMA_BF16(c, a, b0, b1) \
    asm volatile("mma.sync.aligned.m16n8k16.row.col.f32.bf16.bf16.f32 " \
        "{%0,%1,%2,%3}, {%4,%5,%6,%7}, {%8,%9}, {%0,%1,%2,%3};" \
        : "+f"((c)[0]), "+f"((c)[1]), "+f"((c)[2]), "+f"((c)[3]) \
        : "r"((a)[0]), "r"((a)[1]), "r"((a)[2]), "r"((a)[3]), "r"(b0), "r"(b1))

// ---------------- mma.sync GEMM: C[M,N] = A[M,K] * Bt[N,K]^T (+bias) -------
// A split Ah+Al (bf16), Bt split Bh+Bl. D = Ah*Bh + Ah*Bl + Al*Bh.
#define BM 128
#define BN 128
#define BK 32
#define PADK 40                       // 32 + 8 pad: 80B rows, conflict-free ldsm
#define MAT_BYTES (128 * PADK * 2)    // 10240
#define SM_AH 0
#define SM_AL (1 * MAT_BYTES)
#define SM_BH (2 * MAT_BYTES)
#define SM_BL (3 * MAT_BYTES)
#define STAGE_BYTES (4 * MAT_BYTES)   // 40960
#define GEMM_SMEM (2 * STAGE_BYTES)   // 81920

__device__ __forceinline__ void load_chunk(
    uint32_t sb, const __nv_bfloat16* __restrict__ Ah, const __nv_bfloat16* __restrict__ Al,
    const __nv_bfloat16* __restrict__ Bh, const __nv_bfloat16* __restrict__ Bl,
    int brow, int bcol, int K, int kc, int stage, int tid)
{
    uint32_t base = sb + stage * STAGE_BYTES;
#pragma unroll
    for (int t = 0; t < 2; t++) {
        int idx = tid + t * 256;          // 0..511
        int row = idx >> 2;               // 0..127
        int c16 = idx & 3;                // 16B chunk within 64B row
        uint32_t so = (uint32_t)(row * (PADK * 2) + c16 * 16);
        size_t ga = (size_t)(brow + row) * K + kc + c16 * 8;
        size_t gb = (size_t)(bcol + row) * K + kc + c16 * 8;
        cp16(base + SM_AH + so, Ah + ga);
        cp16(base + SM_AL + so, Al + ga);
        cp16(base + SM_BH + so, Bh + gb);
        cp16(base + SM_BL + so, Bl + gb);
    }
}

__global__ __launch_bounds__(256)
void gemm_mma(const __nv_bfloat16* __restrict__ Ah, const __nv_bfloat16* __restrict__ Al,
              const __nv_bfloat16* __restrict__ Bh, const __nv_bfloat16* __restrict__ Bl,
              float* __restrict__ C, int M, int N, int K, const float* __restrict__ bias)
{
    extern __shared__ __align__(128) char smem[];
    uint32_t sb = smem_u32(smem);
    const int tid  = threadIdx.x;
    const int wid  = tid >> 5;
    const int lane = tid & 31;
    const int wm = (wid >> 2) * 64;       // warp row offset in tile (0/64)
    const int wn = (wid & 3) * 32;        // warp col offset in tile
    const int brow = blockIdx.y * BM, bcol = blockIdx.x * BN;

    float c[4][4][4];
#pragma unroll
    for (int i = 0; i < 4; i++)
#pragma unroll
        for (int j = 0; j < 4; j++)
#pragma unroll
            for (int r = 0; r < 4; r++) c[i][j][r] = 0.0f;

    const int nchunks = K / BK;           // 32
    load_chunk(sb, Ah, Al, Bh, Bl, brow, bcol, K, 0, 0, tid);
    CP_COMMIT();
    load_chunk(sb, Ah, Al, Bh, Bl, brow, bcol, K, BK, 1, tid);
    CP_COMMIT();

    // precomputed ldmatrix lane addressing
    const int a_r = lane & 15;
    const int a_c = (lane >> 4) << 3;
    const int b_r = ((lane < 16) ? (lane & 7) : (8 + (lane & 7)));
    const int b_c = ((lane >> 3) & 1) << 3;

    for (int ch = 0; ch < nchunks; ch++) {
        if (ch + 1 < nchunks) { CP_WAIT(1); } else { CP_WAIT(0); }
        __syncthreads();
        uint32_t stb = sb + (ch & 1) * STAGE_BYTES;

#pragma unroll
        for (int ks = 0; ks < 2; ks++) {
            const int kb = ks * 16;
            uint32_t ah[4][4], al[4][4], bh[2][4], bl[2][4];
#pragma unroll
            for (int mt = 0; mt < 4; mt++) {
                uint32_t ad = stb + SM_AH +
                    (uint32_t)((wm + mt * 16 + a_r) * (PADK * 2) + (kb + a_c) * 2);
                LDSM_X4(ah[mt], ad);
                LDSM_X4(al[mt], ad + (SM_AL - SM_AH));
            }
#pragma unroll
            for (int nt = 0; nt < 2; nt++) {
                uint32_t bd = stb + SM_BH +
                    (uint32_t)((wn + nt * 16 + b_r) * (PADK * 2) + (kb + b_c) * 2);
                LDSM_X4(bh[nt], bd);
                LDSM_X4(bl[nt], bd + (SM_BL - SM_BH));
            }
#pragma unroll
            for (int mt = 0; mt < 4; mt++)
#pragma unroll
                for (int n8 = 0; n8 < 4; n8++) {
                    uint32_t bh0 = bh[n8 >> 1][(n8 & 1) * 2];
                    uint32_t bh1 = bh[n8 >> 1][(n8 & 1) * 2 + 1];
                    uint32_t bl0 = bl[n8 >> 1][(n8 & 1) * 2];
                    uint32_t bl1 = bl[n8 >> 1][(n8 & 1) * 2 + 1];
                    MMA_BF16(c[mt][n8], ah[mt], bh0, bh1);
                    MMA_BF16(c[mt][n8], ah[mt], bl0, bl1);
                    MMA_BF16(c[mt][n8], al[mt], bh0, bh1);
                }
        }
        __syncthreads();
        if (ch + 2 < nchunks) {
            load_chunk(sb, Ah, Al, Bh, Bl, brow, bcol, K, (ch + 2) * BK, ch & 1, tid);
            CP_COMMIT();
        }
    }

    // epilogue
#pragma unroll
    for (int mt = 0; mt < 4; mt++) {
        int row0 = brow + wm + mt * 16 + (lane >> 2);
#pragma unroll
        for (int n8 = 0; n8 < 4; n8++) {
            int col = bcol + wn + n8 * 8 + (lane & 3) * 2;
            float bx = 0.f, by = 0.f;
            if (bias) { bx = bias[col]; by = bias[col + 1]; }
            *(float2*)(C + (size_t)row0 * N + col) =
                make_float2(c[mt][n8][0] + bx, c[mt][n8][1] + by);
            *(float2*)(C + (size_t)(row0 + 8) * N + col) =
                make_float2(c[mt][n8][2] + bx, c[mt][n8][3] + by);
        }
    }
}

// ---------------- fp32 -> bf16 hi/lo split kernels --------------------------
__global__ void split_rows(const float* __restrict__ src,
                           __nv_bfloat16* __restrict__ h, __nv_bfloat16* __restrict__ l, int n)
{
    int i = blockIdx.x * blockDim.x + threadIdx.x;
    if (i >= n) return;
    float v = src[i];
    __nv_bfloat16 hb = __float2bfloat16(v);
    h[i] = hb;
    l[i] = __float2bfloat16(v - __bfloat162float(hb));
}

// W[K][N] -> out[N][K] transposed split
__global__ void split_T(const float* __restrict__ W,
                        __nv_bfloat16* __restrict__ h, __nv_bfloat16* __restrict__ l,
                        int K, int N)
{
    int i = blockIdx.x * blockDim.x + threadIdx.x;
    if (i >= N * K) return;
    int n = i / K, k = i - n * K;
    float v = W[(size_t)k * N + n];
    __nv_bfloat16 hb = __float2bfloat16(v);
    h[i] = hb;
    l[i] = __float2bfloat16(v - __bfloat162float(hb));
}

// ---------------- RoPE (in-place on Q,K in g_qkv) ---------------------------
__global__ void rope_kernel()
{
    int idx = blockIdx.x * blockDim.x + threadIdx.x;
    const int total = ROWS * 2 * NHEAD * 32;
    if (idx >= total) return;
    int i = idx & 31;
    int tmp = idx >> 5;
    int h = tmp & (NHEAD - 1);
    tmp >>= 4;
    int comp = tmp & 1;
    int row = tmp >> 1;
    int t = row & (TSEQ - 1);

    float e = (float)(2 * i) * (1.0f / 64.0f);
    float inv_freq = exp2f(-e * 13.2877123795494493f);
    float ang = (float)t * inv_freq;
    float c, s;
    sincosf(ang, &s, &c);

    float* base = g_qkv + (size_t)row * QKVCOLS + comp * DMODEL + h * HD;
    float x1 = base[i];
    float x2 = base[i + 32];
    base[i]      = x1 * c - x2 * s;
    base[i + 32] = x1 * s + x2 * c;
}

// ---------------- sliding-window attention, 32-key blocks -------------------
// One warp per (b,h,t). Lane owns dims {2l,2l+1} for loads; scores are
// transpose-reduced so key j of the block lands on lane j (1 exp / 32 keys).
__global__ __launch_bounds__(256)
void attn_kernel()
{
    int w = (blockIdx.x * blockDim.x + threadIdx.x) >> 5;
    int lane = threadIdx.x & 31;
    int t = w & (TSEQ - 1);
    int tmp = w >> 11;
    int h = tmp & (NHEAD - 1);
    int b = tmp >> 4;

    const float* qp = g_qkv + (size_t)(b * TSEQ + t) * QKVCOLS + h * HD + 2 * lane;
    float2 q = *(const float2*)qp;
    q.x *= 0.125f;
    q.y *= 0.125f;

    int j0 = t - WIN; if (j0 < 0) j0 = 0;
    int j1 = t + WIN; if (j1 > TSEQ - 1) j1 = TSEQ - 1;
    int jb0 = j0 & ~31;

    const float* kbase = g_qkv + (size_t)b * TSEQ * QKVCOLS + DMODEL + h * HD + 2 * lane;

    float m = -INFINITY, l = 0.0f;
    float2 acc = {0.0f, 0.0f};

    for (int jb = jb0; jb <= j1; jb += 32) {
        // per-lane partial scores for 32 keys
        float s[32];
#pragma unroll
        for (int j = 0; j < 32; j++) {
            int kc = jb + j; if (kc > TSEQ - 1) kc = TSEQ - 1;   // clamp OOB loads
            float2 kv = *(const float2*)(kbase + (size_t)kc * QKVCOLS);
            s[j] = q.x * kv.x + q.y * kv.y;
        }
        // butterfly transpose-reduce: s[0] on lane l = full score of key jb+l
#pragma unroll
        for (int off = 16; off >= 1; off >>= 1) {
            bool hi = (lane & off) != 0;
#pragma unroll
            for (int j = 0; j < off; j++) {
                float send = hi ? s[j] : s[j + off];
                float keep = hi ? s[j + off] : s[j];
                float recv = __shfl_xor_sync(0xffffffffu, send, off);
                s[j] = keep + recv;
            }
        }
        float sc = s[0];
        int key = jb + lane;
        if (key < j0 || key > j1) sc = -INFINITY;

        // block max (warp-uniform result)
        float mb = sc;
#pragma unroll
        for (int off = 16; off; off >>= 1)
            mb = fmaxf(mb, __shfl_xor_sync(0xffffffffu, mb, off));
        if (mb > m) {
            float corr = __expf(m - mb);
            l *= corr; acc.x *= corr; acc.y *= corr;
            m = mb;
        }
        float p = __expf(sc - m);   // one exp per lane per 32 keys
        l += p;                     // l kept distributed per lane

        // V accumulation: broadcast p_j, coalesced V loads
#pragma unroll
        for (int j = 0; j < 32; j++) {
            float pj = __shfl_sync(0xffffffffu, p, j);
            int kc = jb + j; if (kc > TSEQ - 1) kc = TSEQ - 1;
            float2 vv = *(const float2*)(kbase + DMODEL + (size_t)kc * QKVCOLS);
            acc.x = fmaf(pj, vv.x, acc.x);
            acc.y = fmaf(pj, vv.y, acc.y);
        }
    }
    // final reduce of distributed l
#pragma unroll
    for (int off = 16; off; off >>= 1)
        l += __shfl_xor_sync(0xffffffffu, l, off);
    float inv = 1.0f / l;
    *(float2*)(g_attn + (size_t)(b * TSEQ + t) * DMODEL + h * HD + 2 * lane) =
        make_float2(acc.x * inv, acc.y * inv);
}

// ---------------------------------------------------------------------------
extern "C" void kernel_launch(void* const* d_in, const int* in_sizes, int n_in,
                              void* d_out, int out_size)
{
    const float* x    = (const float*)d_in[0];
    const float* Wqkv = (const float*)d_in[1];
    const float* Wout = (const float*)d_in[2];
    const float* bout = (const float*)d_in[3];
    float* out = (float*)d_out;

    float *qkv, *attn;
    __nv_bfloat16 *Ah, *Al, *Bh, *Bl;
    cudaGetSymbolAddress((void**)&qkv,  g_qkv);
    cudaGetSymbolAddress((void**)&attn, g_attn);
    cudaGetSymbolAddress((void**)&Ah, g_Ah);
    cudaGetSymbolAddress((void**)&Al, g_Al);
    cudaGetSymbolAddress((void**)&Bh, g_Bh);
    cudaGetSymbolAddress((void**)&Bl, g_Bl);

    cudaFuncSetAttribute(gemm_mma, cudaFuncAttributeMaxDynamicSharedMemorySize, GEMM_SMEM);

    // QKV projection (tensor cores, 3-term bf16 split)
    split_rows<<<(ROWS * DMODEL + 511) / 512, 512>>>(x, Ah, Al, ROWS * DMODEL);
    split_T  <<<(QKVCOLS * DMODEL + 511) / 512, 512>>>(Wqkv, Bh, Bl, DMODEL, QKVCOLS);
    gemm_mma<<<dim3(QKVCOLS / BN, ROWS / BM), 256, GEMM_SMEM>>>(
        Ah, Al, Bh, Bl, qkv, ROWS, QKVCOLS, DMODEL, nullptr);

    // RoPE
    {
        int total = ROWS * 2 * NHEAD * 32;
        rope_kernel<<<(total + 255) / 256, 256>>>();
    }
    // Attention
    attn_kernel<<<(NB * NHEAD * TSEQ) / 8, 256>>>();

    // Output projection
    split_rows<<<(ROWS * DMODEL + 511) / 512, 512>>>(attn, Ah, Al, ROWS * DMODEL);
    split_T  <<<(DMODEL * DMODEL + 511) / 512, 512>>>(Wout, Bh, Bl, DMODEL, DMODEL);
    gemm_mma<<<dim3(DMODEL / BN, ROWS / BM), 256, GEMM_SMEM>>>(
        Ah, Al, Bh, Bl, out, ROWS, DMODEL, DMODEL, bout);
}

// round 4
// speedup vs baseline: 2.7176x; 1.5476x over previous
#include <cuda_runtime.h>
#include <cuda_fp16.h>
#include <math.h>
#include <stdint.h>

#define NB      4
#define TSEQ    2048
#define NHEAD   16
#define HD      64
#define DMODEL  1024
#define ROWS    (NB * TSEQ)          // 8192
#define QKVCOLS (3 * DMODEL)         // 3072
#define WIN     128

// ---------------- scratch (allocation-free rule: device globals) ----------
__device__ float g_qkv [ROWS * QKVCOLS];                 // [b,t, 3,h,d] (un-roped)
__device__ float g_attn[ROWS * DMODEL];                  // [b,t, h,d]
__device__ __align__(16) __half g_Ah[ROWS   * DMODEL];
__device__ __align__(16) __half g_Al[ROWS   * DMODEL];
__device__ __align__(16) __half g_Bh[QKVCOLS * DMODEL];  // [N][K] transposed fp16
__device__ float4 g_rope[TSEQ * 16];  // per (t, pairgrp): (cos_j, sin_j, cos_j+1, sin_j+1)

// ---------------- PTX helpers ---------------------------------------------
__device__ __forceinline__ uint32_t smem_u32(const void* p) {
    uint32_t a;
    asm("{ .reg .u64 t; cvta.to.shared.u64 t, %1; cvt.u32.u64 %0, t; }" : "=r"(a) : "l"(p));
    return a;
}
__device__ __forceinline__ void cp16(uint32_t dst, const void* src) {
    asm volatile("cp.async.cg.shared.global [%0], [%1], 16;" :: "r"(dst), "l"(src));
}
#define CP_COMMIT() asm volatile("cp.async.commit_group;" ::: "memory")
#define CP_WAIT(n)  asm volatile("cp.async.wait_group %0;" :: "n"(n) : "memory")

#define LDSM_X4(r, addr) \
    asm volatile("ldmatrix.sync.aligned.m8n8.x4.shared.b16 {%0,%1,%2,%3}, [%4];" \
        : "=r"((r)[0]), "=r"((r)[1]), "=r"((r)[2]), "=r"((r)[3]) : "r"(addr))

#define MMA_F16(c, a, b0, b1) \
    asm volatile("mma.sync.aligned.m16n8k16.row.col.f32.f16.f16.f32 " \
        "{%0,%1,%2,%3}, {%4,%5,%6,%7}, {%8,%9}, {%0,%1,%2,%3};" \
        : "+f"((c)[0]), "+f"((c)[1]), "+f"((c)[2]), "+f"((c)[3]) \
        : "r"((a)[0]), "r"((a)[1]), "r"((a)[2]), "r"((a)[3]), "r"(b0), "r"(b1))

// ---------------- mma.sync GEMM: C = A[M,K]*Bt[N,K]^T (+bias), fp16 2-term --
#define BM 128
#define BN 128
#define BK 32
#define PADK 40                       // 80B rows, conflict-free ldmatrix
#define MAT_BYTES (128 * PADK * 2)    // 10240
#define SM_AH 0
#define SM_AL (1 * MAT_BYTES)
#define SM_BH (2 * MAT_BYTES)
#define STAGE_BYTES (3 * MAT_BYTES)   // 30720
#define GEMM_SMEM (2 * STAGE_BYTES)   // 61440

__device__ __forceinline__ void load_chunk(
    uint32_t sb, const __half* __restrict__ Ah, const __half* __restrict__ Al,
    const __half* __restrict__ Bh,
    int brow, int bcol, int K, int kc, int stage, int tid)
{
    uint32_t base = sb + stage * STAGE_BYTES;
#pragma unroll
    for (int t = 0; t < 2; t++) {
        int idx = tid + t * 256;          // 0..511
        int row = idx >> 2;               // 0..127
        int c16 = idx & 3;                // 16B chunk in 64B row
        uint32_t so = (uint32_t)(row * (PADK * 2) + c16 * 16);
        size_t ga = (size_t)(brow + row) * K + kc + c16 * 8;
        size_t gb = (size_t)(bcol + row) * K + kc + c16 * 8;
        cp16(base + SM_AH + so, Ah + ga);
        cp16(base + SM_AL + so, Al + ga);
        cp16(base + SM_BH + so, Bh + gb);
    }
}

__global__ __launch_bounds__(256)
void gemm_mma(const __half* __restrict__ Ah, const __half* __restrict__ Al,
              const __half* __restrict__ Bh,
              float* __restrict__ C, int M, int N, int K, const float* __restrict__ bias)
{
    extern __shared__ __align__(128) char smem[];
    uint32_t sb = smem_u32(smem);
    const int tid  = threadIdx.x;
    const int wid  = tid >> 5;
    const int lane = tid & 31;
    const int wm = (wid >> 2) * 64;
    const int wn = (wid & 3) * 32;
    const int brow = blockIdx.y * BM, bcol = blockIdx.x * BN;

    float c[4][4][4];
#pragma unroll
    for (int i = 0; i < 4; i++)
#pragma unroll
        for (int j = 0; j < 4; j++)
#pragma unroll
            for (int r = 0; r < 4; r++) c[i][j][r] = 0.0f;

    const int nchunks = K / BK;
    load_chunk(sb, Ah, Al, Bh, brow, bcol, K, 0, 0, tid);
    CP_COMMIT();
    load_chunk(sb, Ah, Al, Bh, brow, bcol, K, BK, 1, tid);
    CP_COMMIT();

    const int a_r = lane & 15;
    const int a_c = (lane >> 4) << 3;
    const int b_r = ((lane < 16) ? (lane & 7) : (8 + (lane & 7)));
    const int b_c = ((lane >> 3) & 1) << 3;

    for (int ch = 0; ch < nchunks; ch++) {
        if (ch + 1 < nchunks) { CP_WAIT(1); } else { CP_WAIT(0); }
        __syncthreads();
        uint32_t stb = sb + (ch & 1) * STAGE_BYTES;

#pragma unroll
        for (int ks = 0; ks < 2; ks++) {
            const int kb = ks * 16;
            uint32_t ah[4][4], al[4][4], bh[2][4];
#pragma unroll
            for (int mt = 0; mt < 4; mt++) {
                uint32_t ad = stb + SM_AH +
                    (uint32_t)((wm + mt * 16 + a_r) * (PADK * 2) + (kb + a_c) * 2);
                LDSM_X4(ah[mt], ad);
                LDSM_X4(al[mt], ad + (SM_AL - SM_AH));
            }
#pragma unroll
            for (int nt = 0; nt < 2; nt++) {
                uint32_t bd = stb + SM_BH +
                    (uint32_t)((wn + nt * 16 + b_r) * (PADK * 2) + (kb + b_c) * 2);
                LDSM_X4(bh[nt], bd);
            }
#pragma unroll
            for (int mt = 0; mt < 4; mt++)
#pragma unroll
                for (int n8 = 0; n8 < 4; n8++) {
                    uint32_t b0 = bh[n8 >> 1][(n8 & 1) * 2];
                    uint32_t b1 = bh[n8 >> 1][(n8 & 1) * 2 + 1];
                    MMA_F16(c[mt][n8], ah[mt], b0, b1);
                    MMA_F16(c[mt][n8], al[mt], b0, b1);
                }
        }
        __syncthreads();
        if (ch + 2 < nchunks) {
            load_chunk(sb, Ah, Al, Bh, brow, bcol, K, (ch + 2) * BK, ch & 1, tid);
            CP_COMMIT();
        }
    }

#pragma unroll
    for (int mt = 0; mt < 4; mt++) {
        int row0 = brow + wm + mt * 16 + (lane >> 2);
#pragma unroll
        for (int n8 = 0; n8 < 4; n8++) {
            int col = bcol + wn + n8 * 8 + (lane & 3) * 2;
            float bx = 0.f, by = 0.f;
            if (bias) { bx = bias[col]; by = bias[col + 1]; }
            *(float2*)(C + (size_t)row0 * N + col) =
                make_float2(c[mt][n8][0] + bx, c[mt][n8][1] + by);
            *(float2*)(C + (size_t)(row0 + 8) * N + col) =
                make_float2(c[mt][n8][2] + bx, c[mt][n8][3] + by);
        }
    }
}

// ---------------- fp32 -> fp16 hi/lo split (linear, coalesced) --------------
__global__ void split_a(const float* __restrict__ src,
                        __half* __restrict__ h, __half* __restrict__ l, int n)
{
    int i = blockIdx.x * blockDim.x + threadIdx.x;
    if (i >= n) return;
    float v = src[i];
    __half hb = __float2half(v);
    h[i] = hb;
    l[i] = __float2half(v - __half2float(hb));
}

// W[K][N] -> Bt[N][K] fp16, smem-tiled transpose (both sides coalesced)
__global__ void wconv(const float* __restrict__ W, __half* __restrict__ Bt, int K, int N)
{
    __shared__ float tile[32][33];
    int n0 = blockIdx.x * 32, k0 = blockIdx.y * 32;
    int tx = threadIdx.x & 31, ty = threadIdx.x >> 5;   // 256 thr: 32x8
#pragma unroll
    for (int r = 0; r < 4; r++)
        tile[ty + 8 * r][tx] = W[(size_t)(k0 + ty + 8 * r) * N + n0 + tx];
    __syncthreads();
#pragma unroll
    for (int r = 0; r < 4; r++)
        Bt[(size_t)(n0 + ty + 8 * r) * K + k0 + tx] = __float2half(tile[tx][ty + 8 * r]);
}

// ---------------- RoPE cos/sin table ----------------------------------------
__global__ void rope_table()
{
    int idx = blockIdx.x * blockDim.x + threadIdx.x;
    if (idx >= TSEQ * 16) return;
    int t = idx >> 4, pg = idx & 15;
    float c0, s0, c1, s1;
    {
        float e = (float)(2 * (2 * pg)) * (1.0f / 64.0f);
        float ang = (float)t * exp2f(-e * 13.2877123795494493f);
        sincosf(ang, &s0, &c0);
    }
    {
        float e = (float)(2 * (2 * pg + 1)) * (1.0f / 64.0f);
        float ang = (float)t * exp2f(-e * 13.2877123795494493f);
        sincosf(ang, &s1, &c1);
    }
    g_rope[idx] = make_float4(c0, s0, c1, s1);
}

// ---------------- sliding-window attention (smem-tiled, fused RoPE) ---------
// CTA: 64 queries of one (b,h). 8 warps x 8 queries. K/V chunks of 128 keys in
// smem; K roped at fill time. Scores: lane holds 4 q-dims (4*(lane&15)..+3);
// per key-subblock of 32, 16-lane transpose-reduce lands key kb+2j+h on lane.
#define NQ 8
#define CHUNK 128
#define ATTN_SMEM (2 * CHUNK * HD * 4)   // 64 KB

__global__ __launch_bounds__(256, 2)
void attn_kernel()
{
    extern __shared__ float asmem[];
    float* Ks = asmem;                 // [128][64]
    float* Vs = asmem + CHUNK * HD;    // [128][64]

    const int tid = threadIdx.x;
    const int wid = tid >> 5, lane = tid & 31;
    const int b = blockIdx.z, h = blockIdx.y;
    const int t0 = blockIdx.x * 64;
    const int qw = t0 + wid * NQ;      // warp's first query
    const int m4 = lane & 15;
    const int half = lane >> 4;
    const int klane = 2 * m4 + half;   // key index owned by this lane post-reduce

    // ---- load + rope q (duplicated across halves; lane holds dims 4*m4..+3)
    float4 q[NQ];
    float2 acc[NQ];
    float m[NQ], l[NQ], p[NQ];
    const float sgn = (m4 < 8) ? -1.0f : 1.0f;
    const int fq = 2 * (m4 & 7);       // rope table pg for freqs 4*(m4&7)..
#pragma unroll
    for (int i = 0; i < NQ; i++) {
        int t = qw + i;
        const float* qrow = g_qkv + (size_t)(b * TSEQ + t) * QKVCOLS + h * HD;
        float4 qv = *(const float4*)(qrow + 4 * m4);
        float4 cs0 = g_rope[t * 16 + fq];
        float4 cs1 = g_rope[t * 16 + fq + 1];
        float4 pv;
        pv.x = __shfl_xor_sync(0xffffffffu, qv.x, 8);
        pv.y = __shfl_xor_sync(0xffffffffu, qv.y, 8);
        pv.z = __shfl_xor_sync(0xffffffffu, qv.z, 8);
        pv.w = __shfl_xor_sync(0xffffffffu, qv.w, 8);
        q[i].x = 0.125f * fmaf(sgn * pv.x, cs0.y, qv.x * cs0.x);
        q[i].y = 0.125f * fmaf(sgn * pv.y, cs0.w, qv.y * cs0.z);
        q[i].z = 0.125f * fmaf(sgn * pv.z, cs1.y, qv.z * cs1.x);
        q[i].w = 0.125f * fmaf(sgn * pv.w, cs1.w, qv.w * cs1.z);
        acc[i] = make_float2(0.f, 0.f);
        m[i] = -1e30f;
        l[i] = 0.f;
    }

    const float* kvbase = g_qkv + (size_t)b * TSEQ * QKVCOLS + h * HD;

    for (int c = 0; c < 3; c++) {
        int cb = t0 - 128 + c * CHUNK;
        if (cb + CHUNK <= 0 || cb >= TSEQ) continue;   // CTA-uniform
        __syncthreads();
        // ---- fill K (roped) and V
        for (int idx = tid; idx < CHUNK * 16; idx += 256) {
            int key = idx >> 4, pg = idx & 15;
            int kc = cb + key; kc = kc < 0 ? 0 : (kc > TSEQ - 1 ? TSEQ - 1 : kc);
            const float* kr = kvbase + (size_t)kc * QKVCOLS + DMODEL;
            float2 u = *(const float2*)(kr + 2 * pg);
            float2 w = *(const float2*)(kr + 2 * pg + 32);
            float4 cs = g_rope[kc * 16 + pg];
            float* kd = Ks + key * HD;
            kd[2 * pg]      = u.x * cs.x - w.x * cs.y;
            kd[2 * pg + 1]  = u.y * cs.z - w.y * cs.w;
            kd[2 * pg + 32] = u.x * cs.y + w.x * cs.x;
            kd[2 * pg + 33] = u.y * cs.w + w.y * cs.z;
        }
        for (int idx = tid; idx < CHUNK * 16; idx += 256) {
            int key = idx >> 4, grp = idx & 15;
            int kc = cb + key; kc = kc < 0 ? 0 : (kc > TSEQ - 1 ? TSEQ - 1 : kc);
            const float* vr = kvbase + (size_t)kc * QKVCOLS + 2 * DMODEL;
            *(float4*)(Vs + key * HD + 4 * grp) = *(const float4*)(vr + 4 * grp);
        }
        __syncthreads();

        for (int kb = 0; kb < CHUNK; kb += 32) {
            int kg0 = cb + kb;
            if (kg0 + 31 < qw - WIN || kg0 > qw + (NQ - 1) + WIN) continue;  // warp-uniform
            int kg = kg0 + klane;

#pragma unroll
            for (int i = 0; i < NQ; i++) {
                float s[16];
#pragma unroll
                for (int bb = 0; bb < 16; bb++) {
                    float4 k4 = *(const float4*)(Ks + (kb + 2 * bb + half) * HD + 4 * m4);
                    s[bb] = q[i].x * k4.x + q[i].y * k4.y + q[i].z * k4.z + q[i].w * k4.w;
                }
#pragma unroll
                for (int off = 8; off >= 1; off >>= 1) {
                    bool hi = (lane & off) != 0;
#pragma unroll
                    for (int bb = 0; bb < off; bb++) {
                        float send = hi ? s[bb] : s[bb + off];
                        float keep = hi ? s[bb + off] : s[bb];
                        s[bb] = keep + __shfl_xor_sync(0xffffffffu, send, off);
                    }
                }
                float sc = s[0];
                int ti = qw + i;
                bool valid = (kg >= ti - WIN) && (kg <= ti + WIN) && (kg >= 0) && (kg < TSEQ);
                if (!valid) sc = -1e30f;
                float mb = sc;
#pragma unroll
                for (int off = 16; off; off >>= 1)
                    mb = fmaxf(mb, __shfl_xor_sync(0xffffffffu, mb, off));
                if (mb > m[i]) {
                    float corr = __expf(m[i] - mb);
                    l[i] *= corr; acc[i].x *= corr; acc[i].y *= corr;
                    m[i] = mb;
                }
                p[i] = valid ? __expf(sc - m[i]) : 0.f;
                l[i] += p[i];
            }
            // V phase: share each V row across the 8 queries
#pragma unroll
            for (int j = 0; j < 32; j++) {
                float2 vv = *(const float2*)(Vs + (kb + j) * HD + 2 * lane);
                int src = ((j & 1) << 4) | (j >> 1);
#pragma unroll
                for (int i = 0; i < NQ; i++) {
                    float pj = __shfl_sync(0xffffffffu, p[i], src);
                    acc[i].x = fmaf(pj, vv.x, acc[i].x);
                    acc[i].y = fmaf(pj, vv.y, acc[i].y);
                }
            }
        }
    }

#pragma unroll
    for (int i = 0; i < NQ; i++) {
        float ls = l[i];
#pragma unroll
        for (int off = 16; off; off >>= 1)
            ls += __shfl_xor_sync(0xffffffffu, ls, off);
        float inv = 1.0f / ls;
        int t = qw + i;
        *(float2*)(g_attn + (size_t)(b * TSEQ + t) * DMODEL + h * HD + 2 * lane) =
            make_float2(acc[i].x * inv, acc[i].y * inv);
    }
}

// ---------------------------------------------------------------------------
extern "C" void kernel_launch(void* const* d_in, const int* in_sizes, int n_in,
                              void* d_out, int out_size)
{
    const float* x    = (const float*)d_in[0];
    const float* Wqkv = (const float*)d_in[1];
    const float* Wout = (const float*)d_in[2];
    const float* bout = (const float*)d_in[3];
    float* out = (float*)d_out;

    float *qkv, *attn;
    __half *Ah, *Al, *Bh;
    cudaGetSymbolAddress((void**)&qkv,  g_qkv);
    cudaGetSymbolAddress((void**)&attn, g_attn);
    cudaGetSymbolAddress((void**)&Ah, g_Ah);
    cudaGetSymbolAddress((void**)&Al, g_Al);
    cudaGetSymbolAddress((void**)&Bh, g_Bh);

    cudaFuncSetAttribute(gemm_mma, cudaFuncAttributeMaxDynamicSharedMemorySize, GEMM_SMEM);
    cudaFuncSetAttribute(attn_kernel, cudaFuncAttributeMaxDynamicSharedMemorySize, ATTN_SMEM);

    rope_table<<<(TSEQ * 16 + 255) / 256, 256>>>();

    // QKV projection (fp16 2-term)
    split_a<<<(ROWS * DMODEL + 511) / 512, 512>>>(x, Ah, Al, ROWS * DMODEL);
    wconv<<<dim3(QKVCOLS / 32, DMODEL / 32), 256>>>(Wqkv, Bh, DMODEL, QKVCOLS);
    gemm_mma<<<dim3(QKVCOLS / BN, ROWS / BM), 256, GEMM_SMEM>>>(
        Ah, Al, Bh, qkv, ROWS, QKVCOLS, DMODEL, nullptr);

    // Attention (fused RoPE, smem K/V tiles)
    attn_kernel<<<dim3(TSEQ / 64, NHEAD, NB), 256, ATTN_SMEM>>>();

    // Output projection
    split_a<<<(ROWS * DMODEL + 511) / 512, 512>>>(attn, Ah, Al, ROWS * DMODEL);
    wconv<<<dim3(DMODEL / 32, DMODEL / 32), 256>>>(Wout, Bh, DMODEL, DMODEL);
    gemm_mma<<<dim3(DMODEL / BN, ROWS / BM), 256, GEMM_SMEM>>>(
        Ah, Al, Bh, out, ROWS, DMODEL, DMODEL, bout);
}

// round 5
// speedup vs baseline: 4.9916x; 1.8367x over previous
#include <cuda_runtime.h>
#include <cuda_fp16.h>
#include <math.h>
#include <stdint.h>

#define NB      4
#define TSEQ    2048
#define NHEAD   16
#define HD      64
#define DMODEL  1024
#define ROWS    (NB * TSEQ)          // 8192
#define QKVCOLS (3 * DMODEL)         // 3072
#define WIN     128

// ---------------- scratch (allocation-free rule: device globals) ----------
__device__ __align__(16) __half g_qkvh[ROWS * QKVCOLS];  // [b,t, 3,h,d] fp16 (un-roped)
__device__ __align__(16) __half g_Ah[ROWS   * DMODEL];
__device__ __align__(16) __half g_Al[ROWS   * DMODEL];
__device__ __align__(16) __half g_Bh[QKVCOLS * DMODEL];  // [N][K] transposed fp16
__device__ float4 g_rope[TSEQ * 16];  // (t, pg): cos/sin for freqs 2pg, 2pg+1

// ---------------- PTX helpers ---------------------------------------------
__device__ __forceinline__ uint32_t smem_u32(const void* p) {
    uint32_t a;
    asm("{ .reg .u64 t; cvta.to.shared.u64 t, %1; cvt.u32.u64 %0, t; }" : "=r"(a) : "l"(p));
    return a;
}
__device__ __forceinline__ void cp16(uint32_t dst, const void* src) {
    asm volatile("cp.async.cg.shared.global [%0], [%1], 16;" :: "r"(dst), "l"(src));
}
#define CP_COMMIT() asm volatile("cp.async.commit_group;" ::: "memory")
#define CP_WAIT(n)  asm volatile("cp.async.wait_group %0;" :: "n"(n) : "memory")

#define LDSM_X4(r, addr) \
    asm volatile("ldmatrix.sync.aligned.m8n8.x4.shared.b16 {%0,%1,%2,%3}, [%4];" \
        : "=r"((r)[0]), "=r"((r)[1]), "=r"((r)[2]), "=r"((r)[3]) : "r"(addr))
#define LDSM_X4_T(r, addr) \
    asm volatile("ldmatrix.sync.aligned.m8n8.x4.trans.shared.b16 {%0,%1,%2,%3}, [%4];" \
        : "=r"((r)[0]), "=r"((r)[1]), "=r"((r)[2]), "=r"((r)[3]) : "r"(addr))

#define MMA_F16(c, a, b0, b1) \
    asm volatile("mma.sync.aligned.m16n8k16.row.col.f32.f16.f16.f32 " \
        "{%0,%1,%2,%3}, {%4,%5,%6,%7}, {%8,%9}, {%0,%1,%2,%3};" \
        : "+f"((c)[0]), "+f"((c)[1]), "+f"((c)[2]), "+f"((c)[3]) \
        : "r"((a)[0]), "r"((a)[1]), "r"((a)[2]), "r"((a)[3]), "r"(b0), "r"(b1))

__device__ __forceinline__ uint32_t packh2(float a, float b) {
    __half2 h = __floats2half2_rn(a, b);
    return *reinterpret_cast<uint32_t*>(&h);
}

// ---------------- mma.sync GEMM: C = A[M,K]*Bt[N,K]^T, fp16 2-term A -------
#define BM 128
#define BN 128
#define BK 32
#define PADK 40
#define MAT_BYTES (128 * PADK * 2)    // 10240
#define SM_AH 0
#define SM_AL (1 * MAT_BYTES)
#define SM_BH (2 * MAT_BYTES)
#define STAGE_BYTES (3 * MAT_BYTES)   // 30720
#define GEMM_SMEM (3 * STAGE_BYTES)   // 92160, 3-stage

__device__ __forceinline__ void load_chunk(
    uint32_t sb, const __half* __restrict__ Ah, const __half* __restrict__ Al,
    const __half* __restrict__ Bh,
    int brow, int bcol, int K, int kc, int stage, int tid)
{
    uint32_t base = sb + stage * STAGE_BYTES;
#pragma unroll
    for (int t = 0; t < 2; t++) {
        int idx = tid + t * 256;
        int row = idx >> 2;
        int c16 = idx & 3;
        uint32_t so = (uint32_t)(row * (PADK * 2) + c16 * 16);
        size_t ga = (size_t)(brow + row) * K + kc + c16 * 8;
        size_t gb = (size_t)(bcol + row) * K + kc + c16 * 8;
        cp16(base + SM_AH + so, Ah + ga);
        cp16(base + SM_AL + so, Al + ga);
        cp16(base + SM_BH + so, Bh + gb);
    }
}

__global__ __launch_bounds__(256)
void gemm_mma(const __half* __restrict__ Ah, const __half* __restrict__ Al,
              const __half* __restrict__ Bh,
              float* __restrict__ C, __half* __restrict__ Chalf,
              int M, int N, int K, const float* __restrict__ bias)
{
    extern __shared__ __align__(128) char smem[];
    uint32_t sb = smem_u32(smem);
    const int tid  = threadIdx.x;
    const int wid  = tid >> 5;
    const int lane = tid & 31;
    const int wm = (wid >> 2) * 64;
    const int wn = (wid & 3) * 32;
    const int brow = blockIdx.y * BM, bcol = blockIdx.x * BN;

    float c[4][4][4];
#pragma unroll
    for (int i = 0; i < 4; i++)
#pragma unroll
        for (int j = 0; j < 4; j++)
#pragma unroll
            for (int r = 0; r < 4; r++) c[i][j][r] = 0.0f;

    const int nchunks = K / BK;
    load_chunk(sb, Ah, Al, Bh, brow, bcol, K, 0, 0, tid);
    CP_COMMIT();
    load_chunk(sb, Ah, Al, Bh, brow, bcol, K, BK, 1, tid);
    CP_COMMIT();

    const int a_r = lane & 15;
    const int a_c = (lane >> 4) << 3;
    const int b_r = ((lane < 16) ? (lane & 7) : (8 + (lane & 7)));
    const int b_c = ((lane >> 3) & 1) << 3;

    for (int ch = 0; ch < nchunks; ch++) {
        if (ch + 1 < nchunks) { CP_WAIT(1); } else { CP_WAIT(0); }
        __syncthreads();
        if (ch + 2 < nchunks) {
            load_chunk(sb, Ah, Al, Bh, brow, bcol, K, (ch + 2) * BK, (ch + 2) % 3, tid);
            CP_COMMIT();
        }
        uint32_t stb = sb + (ch % 3) * STAGE_BYTES;
#pragma unroll
        for (int ks = 0; ks < 2; ks++) {
            const int kb = ks * 16;
            uint32_t ah[4][4], al[4][4], bh[2][4];
#pragma unroll
            for (int mt = 0; mt < 4; mt++) {
                uint32_t ad = stb + SM_AH +
                    (uint32_t)((wm + mt * 16 + a_r) * (PADK * 2) + (kb + a_c) * 2);
                LDSM_X4(ah[mt], ad);
                LDSM_X4(al[mt], ad + (SM_AL - SM_AH));
            }
#pragma unroll
            for (int nt = 0; nt < 2; nt++) {
                uint32_t bd = stb + SM_BH +
                    (uint32_t)((wn + nt * 16 + b_r) * (PADK * 2) + (kb + b_c) * 2);
                LDSM_X4(bh[nt], bd);
            }
#pragma unroll
            for (int mt = 0; mt < 4; mt++)
#pragma unroll
                for (int n8 = 0; n8 < 4; n8++) {
                    uint32_t b0 = bh[n8 >> 1][(n8 & 1) * 2];
                    uint32_t b1 = bh[n8 >> 1][(n8 & 1) * 2 + 1];
                    MMA_F16(c[mt][n8], ah[mt], b0, b1);
                    MMA_F16(c[mt][n8], al[mt], b0, b1);
                }
        }
    }

#pragma unroll
    for (int mt = 0; mt < 4; mt++) {
        int row0 = brow + wm + mt * 16 + (lane >> 2);
#pragma unroll
        for (int n8 = 0; n8 < 4; n8++) {
            int col = bcol + wn + n8 * 8 + (lane & 3) * 2;
            if (Chalf) {
                __half2 v0 = __floats2half2_rn(c[mt][n8][0], c[mt][n8][1]);
                __half2 v1 = __floats2half2_rn(c[mt][n8][2], c[mt][n8][3]);
                *(__half2*)(Chalf + (size_t)row0 * N + col) = v0;
                *(__half2*)(Chalf + (size_t)(row0 + 8) * N + col) = v1;
            } else {
                float bx = 0.f, by = 0.f;
                if (bias) { bx = bias[col]; by = bias[col + 1]; }
                *(float2*)(C + (size_t)row0 * N + col) =
                    make_float2(c[mt][n8][0] + bx, c[mt][n8][1] + by);
                *(float2*)(C + (size_t)(row0 + 8) * N + col) =
                    make_float2(c[mt][n8][2] + bx, c[mt][n8][3] + by);
            }
        }
    }
}

// ---------------- fp32 -> fp16 hi/lo split (x input only) -------------------
__global__ void split_a(const float* __restrict__ src,
                        __half* __restrict__ h, __half* __restrict__ l, int n)
{
    int i = blockIdx.x * blockDim.x + threadIdx.x;
    if (i >= n) return;
    float v = src[i];
    __half hb = __float2half(v);
    h[i] = hb;
    l[i] = __float2half(v - __half2float(hb));
}

// W[K][N] -> Bt[N][K] fp16, smem-tiled transpose
__global__ void wconv(const float* __restrict__ W, __half* __restrict__ Bt, int K, int N)
{
    __shared__ float tile[32][33];
    int n0 = blockIdx.x * 32, k0 = blockIdx.y * 32;
    int tx = threadIdx.x & 31, ty = threadIdx.x >> 5;
#pragma unroll
    for (int r = 0; r < 4; r++)
        tile[ty + 8 * r][tx] = W[(size_t)(k0 + ty + 8 * r) * N + n0 + tx];
    __syncthreads();
#pragma unroll
    for (int r = 0; r < 4; r++)
        Bt[(size_t)(n0 + ty + 8 * r) * K + k0 + tx] = __float2half(tile[tx][ty + 8 * r]);
}

// ---------------- RoPE cos/sin table ----------------------------------------
__global__ void rope_table()
{
    int idx = blockIdx.x * blockDim.x + threadIdx.x;
    if (idx >= TSEQ * 16) return;
    int t = idx >> 4, pg = idx & 15;
    float c0, s0, c1, s1;
    {
        float e = (float)(2 * (2 * pg)) * (1.0f / 64.0f);
        float ang = (float)t * exp2f(-e * 13.2877123795494493f);
        sincosf(ang, &s0, &c0);
    }
    {
        float e = (float)(2 * (2 * pg + 1)) * (1.0f / 64.0f);
        float ang = (float)t * exp2f(-e * 13.2877123795494493f);
        sincosf(ang, &s1, &c1);
    }
    g_rope[idx] = make_float4(c0, s0, c1, s1);
}

// ---------------- flash attention via mma.sync -------------------------------
// CTA: 64 queries of one (b,h). Whole 320-key window resident in smem fp16.
// Warps: 4m x 2n. Warp = 16q x 32k slab per 64-key chunk, online softmax in
// fragments, PV mma, cross-warp_n merge at end. Writes Ah/Al hi/lo fp16 split.
#define PADH 72
#define QS_BYTES (64 * PADH * 2)        // 9216
#define KS_OFF   QS_BYTES
#define KS_BYTES (320 * PADH * 2)       // 46080
#define VS_OFF   (KS_OFF + KS_BYTES)
#define ATTN_SMEM (VS_OFF + KS_BYTES)   // 101376

__global__ __launch_bounds__(256, 2)
void attn_kernel()
{
    extern __shared__ __align__(128) char asmem[];
    uint32_t sb = smem_u32(asmem);
    __half* Qs  = (__half*)asmem;
    __half* Ksm = (__half*)(asmem + KS_OFF);
    __half* Vsm = (__half*)(asmem + VS_OFF);
    float*  mgb = (float*)(asmem + KS_OFF);   // merge buffer aliases Ks

    const int tid = threadIdx.x, wid = tid >> 5, lane = tid & 31;
    const int b = blockIdx.z, h = blockIdx.y;
    const int t0 = blockIdx.x * 64;
    const int warp_m = wid & 3, warp_n = wid >> 2;

    const __half* qkbase = g_qkvh + (size_t)b * TSEQ * QKVCOLS + h * HD;

    // ---- fill Q (rope + scale)
    for (int idx = tid; idx < 64 * 16; idx += 256) {
        int qr = idx >> 4, pg = idx & 15;
        int t = t0 + qr;
        const __half* src = qkbase + (size_t)t * QKVCOLS;
        float2 u = __half22float2(*(const __half2*)(src + 2 * pg));
        float2 w = __half22float2(*(const __half2*)(src + 2 * pg + 32));
        float4 cs = g_rope[t * 16 + pg];
        *(__half2*)(Qs + qr * PADH + 2 * pg) = __floats2half2_rn(
            0.125f * (u.x * cs.x - w.x * cs.y), 0.125f * (u.y * cs.z - w.y * cs.w));
        *(__half2*)(Qs + qr * PADH + 2 * pg + 32) = __floats2half2_rn(
            0.125f * (u.x * cs.y + w.x * cs.x), 0.125f * (u.y * cs.w + w.y * cs.z));
    }
    // ---- fill K (rope) over keys [t0-128, t0+192), clamped
    for (int idx = tid; idx < 320 * 16; idx += 256) {
        int kk = idx >> 4, pg = idx & 15;
        int kg = t0 - 128 + kk;
        kg = kg < 0 ? 0 : (kg > TSEQ - 1 ? TSEQ - 1 : kg);
        const __half* src = qkbase + (size_t)kg * QKVCOLS + DMODEL;
        float2 u = __half22float2(*(const __half2*)(src + 2 * pg));
        float2 w = __half22float2(*(const __half2*)(src + 2 * pg + 32));
        float4 cs = g_rope[kg * 16 + pg];
        *(__half2*)(Ksm + kk * PADH + 2 * pg) = __floats2half2_rn(
            u.x * cs.x - w.x * cs.y, u.y * cs.z - w.y * cs.w);
        *(__half2*)(Ksm + kk * PADH + 2 * pg + 32) = __floats2half2_rn(
            u.x * cs.y + w.x * cs.x, u.y * cs.w + w.y * cs.z);
    }
    // ---- fill V
    for (int idx = tid; idx < 320 * 8; idx += 256) {
        int kk = idx >> 3, grp = idx & 7;
        int kg = t0 - 128 + kk;
        kg = kg < 0 ? 0 : (kg > TSEQ - 1 ? TSEQ - 1 : kg);
        const __half* src = qkbase + (size_t)kg * QKVCOLS + 2 * DMODEL + 8 * grp;
        *(int4*)(Vsm + kk * PADH + 8 * grp) = *(const int4*)src;
    }
    __syncthreads();

    const int a_r = lane & 15;
    const int a_c = (lane >> 4) << 3;
    const int b_r = ((lane < 16) ? (lane & 7) : (8 + (lane & 7)));
    const int b_c = ((lane >> 3) & 1) << 3;
    const int qlo = t0 + warp_m * 16;
    const int qi0 = qlo + (lane >> 2);

    float m0 = -1e30f, m1 = -1e30f, l0 = 0.f, l1 = 0.f;
    float o[8][4];
#pragma unroll
    for (int t = 0; t < 8; t++)
#pragma unroll
        for (int j = 0; j < 4; j++) o[t][j] = 0.f;

    for (int c = 0; c < 5; c++) {
        int kk0 = 64 * c + 32 * warp_n;     // local key index of slab
        int kgb = t0 - 128 + kk0;           // global first key (may be <0)
        if (kgb + 31 < qlo - WIN || kgb > qlo + 15 + WIN) continue;

        // ---- S = Q K^T (16q x 32k)
        float cS[4][4];
#pragma unroll
        for (int i = 0; i < 4; i++)
#pragma unroll
            for (int j = 0; j < 4; j++) cS[i][j] = 0.f;
#pragma unroll
        for (int ks = 0; ks < 4; ks++) {
            uint32_t aq[4], bk0[4], bk1[4];
            LDSM_X4(aq, sb + (uint32_t)((warp_m * 16 + a_r) * PADH + ks * 16 + a_c) * 2);
            LDSM_X4(bk0, sb + KS_OFF + (uint32_t)((kk0 + b_r) * PADH + ks * 16 + b_c) * 2);
            LDSM_X4(bk1, sb + KS_OFF + (uint32_t)((kk0 + 16 + b_r) * PADH + ks * 16 + b_c) * 2);
            MMA_F16(cS[0], aq, bk0[0], bk0[1]);
            MMA_F16(cS[1], aq, bk0[2], bk0[3]);
            MMA_F16(cS[2], aq, bk1[0], bk1[1]);
            MMA_F16(cS[3], aq, bk1[2], bk1[3]);
        }

        // ---- mask + row max
        float rmax0 = -1e30f, rmax1 = -1e30f;
#pragma unroll
        for (int n8 = 0; n8 < 4; n8++) {
            int jb = kgb + 8 * n8 + 2 * (lane & 3);
#pragma unroll
            for (int e = 0; e < 2; e++) {
                int j = jb + e;
                bool okj = (j >= 0) && (j < TSEQ);
                if (!(okj && j >= qi0 - WIN && j <= qi0 + WIN))         cS[n8][e]     = -1e30f;
                if (!(okj && j >= qi0 + 8 - WIN && j <= qi0 + 8 + WIN)) cS[n8][e + 2] = -1e30f;
            }
            rmax0 = fmaxf(rmax0, fmaxf(cS[n8][0], cS[n8][1]));
            rmax1 = fmaxf(rmax1, fmaxf(cS[n8][2], cS[n8][3]));
        }
        rmax0 = fmaxf(rmax0, __shfl_xor_sync(0xffffffffu, rmax0, 1));
        rmax0 = fmaxf(rmax0, __shfl_xor_sync(0xffffffffu, rmax0, 2));
        rmax1 = fmaxf(rmax1, __shfl_xor_sync(0xffffffffu, rmax1, 1));
        rmax1 = fmaxf(rmax1, __shfl_xor_sync(0xffffffffu, rmax1, 2));

        float mn0 = fmaxf(m0, rmax0), mn1 = fmaxf(m1, rmax1);
        float sc0 = __expf(m0 - mn0), sc1 = __expf(m1 - mn1);
        m0 = mn0; m1 = mn1;

        float ps0 = 0.f, ps1 = 0.f;
        uint32_t pa[4][2];
#pragma unroll
        for (int n8 = 0; n8 < 4; n8++) {
            float p0 = (cS[n8][0] < -1e29f) ? 0.f : __expf(cS[n8][0] - mn0);
            float p1 = (cS[n8][1] < -1e29f) ? 0.f : __expf(cS[n8][1] - mn0);
            float p2 = (cS[n8][2] < -1e29f) ? 0.f : __expf(cS[n8][2] - mn1);
            float p3 = (cS[n8][3] < -1e29f) ? 0.f : __expf(cS[n8][3] - mn1);
            ps0 += p0 + p1; ps1 += p2 + p3;
            pa[n8][0] = packh2(p0, p1);
            pa[n8][1] = packh2(p2, p3);
        }
        ps0 += __shfl_xor_sync(0xffffffffu, ps0, 1);
        ps0 += __shfl_xor_sync(0xffffffffu, ps0, 2);
        ps1 += __shfl_xor_sync(0xffffffffu, ps1, 1);
        ps1 += __shfl_xor_sync(0xffffffffu, ps1, 2);
        l0 = l0 * sc0 + ps0;
        l1 = l1 * sc1 + ps1;
#pragma unroll
        for (int t = 0; t < 8; t++) {
            o[t][0] *= sc0; o[t][1] *= sc0; o[t][2] *= sc1; o[t][3] *= sc1;
        }

        // ---- O += P V  (16q x 32k x 64d)
#pragma unroll
        for (int kp = 0; kp < 2; kp++) {
            uint32_t a[4] = { pa[2 * kp][0], pa[2 * kp][1], pa[2 * kp + 1][0], pa[2 * kp + 1][1] };
#pragma unroll
            for (int np = 0; np < 4; np++) {
                uint32_t bv[4];
                LDSM_X4_T(bv, sb + VS_OFF +
                    (uint32_t)((kk0 + kp * 16 + a_r) * PADH + np * 16 + a_c) * 2);
                MMA_F16(o[2 * np],     a, bv[0], bv[1]);
                MMA_F16(o[2 * np + 1], a, bv[2], bv[3]);
            }
        }
    }

    // ---- merge warp_n halves (buffer aliases Ks)
    __syncthreads();
    float* ob = mgb + (warp_m * 32 + lane) * 33;
    float2* mlb = (float2*)(mgb + 4 * 32 * 33);
    if (warp_n == 1) {
#pragma unroll
        for (int t = 0; t < 8; t++)
#pragma unroll
            for (int j = 0; j < 4; j++) ob[4 * t + j] = o[t][j];
        if ((lane & 3) == 0) {
            mlb[warp_m * 16 + (lane >> 2)]     = make_float2(m0, l0);
            mlb[warp_m * 16 + 8 + (lane >> 2)] = make_float2(m1, l1);
        }
    }
    __syncthreads();
    if (warp_n == 0) {
        float2 M0 = mlb[warp_m * 16 + (lane >> 2)];
        float2 M1 = mlb[warp_m * 16 + 8 + (lane >> 2)];
        float mm0 = fmaxf(m0, M0.x), mm1 = fmaxf(m1, M1.x);
        float w00 = __expf(m0 - mm0), w01 = __expf(M0.x - mm0);
        float w10 = __expf(m1 - mm1), w11 = __expf(M1.x - mm1);
        float inv0 = 1.0f / (l0 * w00 + M0.y * w01);
        float inv1 = 1.0f / (l1 * w10 + M1.y * w11);
        size_t r0 = (size_t)(b * TSEQ + qlo + (lane >> 2)) * DMODEL;
        size_t r1 = r0 + 8 * DMODEL;
#pragma unroll
        for (int t = 0; t < 8; t++) {
            int col = h * HD + t * 8 + 2 * (lane & 3);
            float v0 = (o[t][0] * w00 + ob[4 * t + 0] * w01) * inv0;
            float v1 = (o[t][1] * w00 + ob[4 * t + 1] * w01) * inv0;
            float v2 = (o[t][2] * w10 + ob[4 * t + 2] * w11) * inv1;
            float v3 = (o[t][3] * w10 + ob[4 * t + 3] * w11) * inv1;
            __half h0 = __float2half(v0), h1 = __float2half(v1);
            __half h2 = __float2half(v2), h3 = __float2half(v3);
            *(__half2*)(g_Ah + r0 + col) = __halves2half2(h0, h1);
            *(__half2*)(g_Ah + r1 + col) = __halves2half2(h2, h3);
            *(__half2*)(g_Al + r0 + col) = __halves2half2(
                __float2half(v0 - __half2float(h0)), __float2half(v1 - __half2float(h1)));
            *(__half2*)(g_Al + r1 + col) = __halves2half2(
                __float2half(v2 - __half2float(h2)), __float2half(v3 - __half2float(h3)));
        }
    }
}

// ---------------------------------------------------------------------------
extern "C" void kernel_launch(void* const* d_in, const int* in_sizes, int n_in,
                              void* d_out, int out_size)
{
    const float* x    = (const float*)d_in[0];
    const float* Wqkv = (const float*)d_in[1];
    const float* Wout = (const float*)d_in[2];
    const float* bout = (const float*)d_in[3];
    float* out = (float*)d_out;

    __half *qkvh, *Ah, *Al, *Bh;
    cudaGetSymbolAddress((void**)&qkvh, g_qkvh);
    cudaGetSymbolAddress((void**)&Ah, g_Ah);
    cudaGetSymbolAddress((void**)&Al, g_Al);
    cudaGetSymbolAddress((void**)&Bh, g_Bh);

    cudaFuncSetAttribute(gemm_mma, cudaFuncAttributeMaxDynamicSharedMemorySize, GEMM_SMEM);
    cudaFuncSetAttribute(attn_kernel, cudaFuncAttributeMaxDynamicSharedMemorySize, ATTN_SMEM);

    rope_table<<<(TSEQ * 16 + 255) / 256, 256>>>();

    // QKV projection -> fp16 directly
    split_a<<<(ROWS * DMODEL + 511) / 512, 512>>>(x, Ah, Al, ROWS * DMODEL);
    wconv<<<dim3(QKVCOLS / 32, DMODEL / 32), 256>>>(Wqkv, Bh, DMODEL, QKVCOLS);
    gemm_mma<<<dim3(QKVCOLS / BN, ROWS / BM), 256, GEMM_SMEM>>>(
        Ah, Al, Bh, nullptr, qkvh, ROWS, QKVCOLS, DMODEL, nullptr);

    // Flash attention (fused rope), writes Ah/Al for out-proj
    attn_kernel<<<dim3(TSEQ / 64, NHEAD, NB), 256, ATTN_SMEM>>>();

    // Output projection (fp32 out + bias)
    wconv<<<dim3(DMODEL / 32, DMODEL / 32), 256>>>(Wout, Bh, DMODEL, DMODEL);
    gemm_mma<<<dim3(DMODEL / BN, ROWS / BM), 256, GEMM_SMEM>>>(
        Ah, Al, Bh, out, nullptr, ROWS, DMODEL, DMODEL, bout);
}